// round 1
// baseline (speedup 1.0000x reference)
#include <cuda_runtime.h>

#define B 64
#define S 2048
#define D 512
#define U 512

// Scratch (allocation-free rule: __device__ globals)
__device__ float g_Q[B * U];          // query @ W1
__device__ float g_scores[B * S];     // pre-softmax scores
__device__ float g_w[B * S];          // softmax weights
__device__ float g_part[B * 8 * D];   // partial contexts (8 S-splits)

// ---------------------------------------------------------------------------
// K1: Q = query @ W1   (64 x 512) = (64 x 512) @ (512 x 512)
// one CTA per batch row, one thread per output column
// ---------------------------------------------------------------------------
__global__ void q_kernel(const float* __restrict__ query,
                         const float* __restrict__ W1) {
    int b = blockIdx.x;
    int tid = threadIdx.x;
    __shared__ float qs[D];
    qs[tid] = query[b * D + tid];
    __syncthreads();
    float acc = 0.f;
#pragma unroll 8
    for (int d = 0; d < D; ++d) acc += qs[d] * W1[d * U + tid];
    g_Q[b * U + tid] = acc;
}

// ---------------------------------------------------------------------------
// K2: scores[b][s] = V1 . tanh(Q[b] + values[b][s] @ W2)
// Tiled GEMM: per CTA 64 S-rows x 512 U-cols, K-chunk 16, fused epilogue.
// 512 threads: tx in [0,32) -> col groups, ty in [0,16) -> 4 rows each.
// Thread computes 4 rows x 16 cols (cols c = 4*tx + 128*jj + comp).
// ---------------------------------------------------------------------------
#define KC 16

__global__ __launch_bounds__(512, 1) void scores_kernel(
    const float* __restrict__ values, const float* __restrict__ W2,
    const float* __restrict__ V1) {
    int b = blockIdx.y;
    int s0 = blockIdx.x * 64;
    int tid = threadIdx.x;
    int tx = tid & 31;
    int ty = tid >> 5;

    __shared__ float  As[64][KC];        // 4 KB
    __shared__ float4 Bs[KC][U / 4];     // 32 KB

    float4 acc[4][4];
#pragma unroll
    for (int r = 0; r < 4; ++r)
#pragma unroll
        for (int j = 0; j < 4; ++j) acc[r][j] = make_float4(0.f, 0.f, 0.f, 0.f);

    const size_t vbase = ((size_t)b * S + s0) * D;

    for (int k0 = 0; k0 < D; k0 += KC) {
        // Load A tile: 64 rows x 16 k  = 256 float4; threads 0..255
        if (tid < 256) {
            int row = tid >> 2;          // 0..63
            int cg  = tid & 3;           // 0..3
            *(float4*)&As[row][cg * 4] =
                *(const float4*)(values + vbase + (size_t)row * D + k0 + cg * 4);
        }
        // Load B tile: 16 k x 512 u = 2048 float4; 4 per thread, coalesced
        {
            const float4* src = (const float4*)(W2 + (size_t)k0 * U);
            float4* dst = (float4*)Bs;
#pragma unroll
            for (int i = 0; i < 4; ++i) dst[tid + 512 * i] = src[tid + 512 * i];
        }
        __syncthreads();

#pragma unroll
        for (int kk = 0; kk < KC; ++kk) {
            float a0 = As[ty * 4 + 0][kk];
            float a1 = As[ty * 4 + 1][kk];
            float a2 = As[ty * 4 + 2][kk];
            float a3 = As[ty * 4 + 3][kk];
#pragma unroll
            for (int jj = 0; jj < 4; ++jj) {
                float4 bv = Bs[kk][tx + 32 * jj];
                acc[0][jj].x += a0 * bv.x; acc[0][jj].y += a0 * bv.y;
                acc[0][jj].z += a0 * bv.z; acc[0][jj].w += a0 * bv.w;
                acc[1][jj].x += a1 * bv.x; acc[1][jj].y += a1 * bv.y;
                acc[1][jj].z += a1 * bv.z; acc[1][jj].w += a1 * bv.w;
                acc[2][jj].x += a2 * bv.x; acc[2][jj].y += a2 * bv.y;
                acc[2][jj].z += a2 * bv.z; acc[2][jj].w += a2 * bv.w;
                acc[3][jj].x += a3 * bv.x; acc[3][jj].y += a3 * bv.y;
                acc[3][jj].z += a3 * bv.z; acc[3][jj].w += a3 * bv.w;
            }
        }
        __syncthreads();
    }

    // Epilogue: score contribution = sum_c V1[c] * tanh(Q[b][c] + acc)
    const float* Qb = g_Q + b * U;
#pragma unroll
    for (int ri = 0; ri < 4; ++ri) {
        float p = 0.f;
#pragma unroll
        for (int jj = 0; jj < 4; ++jj) {
            int c = tx * 4 + jj * 128;
            float4 q4 = *(const float4*)(Qb + c);
            float4 v4 = *(const float4*)(V1 + c);
            p += v4.x * tanhf(q4.x + acc[ri][jj].x);
            p += v4.y * tanhf(q4.y + acc[ri][jj].y);
            p += v4.z * tanhf(q4.z + acc[ri][jj].z);
            p += v4.w * tanhf(q4.w + acc[ri][jj].w);
        }
#pragma unroll
        for (int off = 16; off; off >>= 1)
            p += __shfl_xor_sync(0xffffffffu, p, off);
        if (tx == 0) g_scores[b * S + s0 + ty * 4 + ri] = p;
    }
}

// ---------------------------------------------------------------------------
// K3a: per-batch softmax over S -> weights g_w
// ---------------------------------------------------------------------------
__global__ void softmax_kernel() {
    int b = blockIdx.x;
    int tid = threadIdx.x;
    __shared__ float sm[S];
    __shared__ float red[16];
    const float* sc = g_scores + b * S;

    float lmax = -1e30f;
    for (int i = tid; i < S; i += 512) {
        float v = sc[i];
        sm[i] = v;
        lmax = fmaxf(lmax, v);
    }
#pragma unroll
    for (int off = 16; off; off >>= 1)
        lmax = fmaxf(lmax, __shfl_xor_sync(0xffffffffu, lmax, off));
    if ((tid & 31) == 0) red[tid >> 5] = lmax;
    __syncthreads();
    float m = -1e30f;
#pragma unroll
    for (int i = 0; i < 16; ++i) m = fmaxf(m, red[i]);
    __syncthreads();

    float lsum = 0.f;
    for (int i = tid; i < S; i += 512) {
        float e = expf(sm[i] - m);
        sm[i] = e;
        lsum += e;
    }
#pragma unroll
    for (int off = 16; off; off >>= 1)
        lsum += __shfl_xor_sync(0xffffffffu, lsum, off);
    if ((tid & 31) == 0) red[tid >> 5] = lsum;
    __syncthreads();
    float tot = 0.f;
#pragma unroll
    for (int i = 0; i < 16; ++i) tot += red[i];
    float inv = 1.f / tot;
    for (int i = tid; i < S; i += 512) g_w[b * S + i] = sm[i] * inv;
}

// ---------------------------------------------------------------------------
// K3b: partial context: each CTA handles one (b, split) over 256 S-rows
// ---------------------------------------------------------------------------
__global__ void context_partial(const float* __restrict__ values) {
    int split = blockIdx.x;   // 0..7
    int b = blockIdx.y;
    int tid = threadIdx.x;    // d index
    const float* wb = g_w + b * S + split * 256;
    const float* vb = values + ((size_t)b * S + (size_t)split * 256) * D + tid;
    float acc = 0.f;
#pragma unroll 4
    for (int s = 0; s < 256; ++s) acc += wb[s] * vb[(size_t)s * D];
    g_part[(b * 8 + split) * D + tid] = acc;
}

// ---------------------------------------------------------------------------
// K3c: reduce 8 partials -> output (B x D)
// ---------------------------------------------------------------------------
__global__ void context_reduce(float* __restrict__ out) {
    int b = blockIdx.x;
    int tid = threadIdx.x;
    float acc = 0.f;
#pragma unroll
    for (int i = 0; i < 8; ++i) acc += g_part[(b * 8 + i) * D + tid];
    out[b * D + tid] = acc;
}

// ---------------------------------------------------------------------------
extern "C" void kernel_launch(void* const* d_in, const int* in_sizes, int n_in,
                              void* d_out, int out_size) {
    const float* query  = (const float*)d_in[0];   // (B, D)
    const float* values = (const float*)d_in[1];   // (B, S, D)
    const float* W1     = (const float*)d_in[2];   // (D, U)
    const float* W2     = (const float*)d_in[3];   // (D, U)
    const float* V1     = (const float*)d_in[4];   // (U, 1)
    float* out = (float*)d_out;                    // (B, D)

    q_kernel<<<B, 512>>>(query, W1);
    scores_kernel<<<dim3(S / 64, B), 512>>>(values, W2, V1);
    softmax_kernel<<<B, 512>>>();
    context_partial<<<dim3(8, B), 512>>>(values);
    context_reduce<<<B, 512>>>(out);
}

// round 6
// speedup vs baseline: 6.0727x; 6.0727x over previous
#include <cuda_runtime.h>
#include <cuda_fp16.h>
#include <cstdint>

#define B 64
#define S 2048
#define D 512
#define U 512

// Scratch (allocation-free rule: __device__ globals)
__device__ float  g_Q[B * U];        // query @ W1
__device__ __half g_W2h[U * D];      // W2 transposed to (U, D), fp16
__device__ float  g_scores[B * S];   // pre-softmax scores (atomically accumulated)
__device__ float  g_w[B * S];        // softmax weights
__device__ float  g_part[B * 8 * D]; // partial contexts

// ---------------------------------------------------------------------------
// Helpers
// ---------------------------------------------------------------------------
__device__ __forceinline__ uint32_t smem_u32(const void* p) {
    uint32_t a;
    asm("{ .reg .u64 t; cvta.to.shared.u64 t, %1; cvt.u32.u64 %0, t; }"
        : "=r"(a) : "l"(p));
    return a;
}
__device__ __forceinline__ float tanh_apx(float x) {
    float y; asm("tanh.approx.f32 %0, %1;" : "=f"(y) : "f"(x)); return y;
}
__device__ __forceinline__ void ldsm_x4(uint32_t* r, uint32_t addr) {
    asm volatile("ldmatrix.sync.aligned.m8n8.x4.shared.b16 {%0,%1,%2,%3}, [%4];"
                 : "=r"(r[0]), "=r"(r[1]), "=r"(r[2]), "=r"(r[3]) : "r"(addr));
}
__device__ __forceinline__ void mma16816(float* c, const uint32_t* a,
                                         uint32_t b0, uint32_t b1) {
    asm volatile(
        "mma.sync.aligned.m16n8k16.row.col.f32.f16.f16.f32 "
        "{%0,%1,%2,%3}, {%4,%5,%6,%7}, {%8,%9}, {%0,%1,%2,%3};"
        : "+f"(c[0]), "+f"(c[1]), "+f"(c[2]), "+f"(c[3])
        : "r"(a[0]), "r"(a[1]), "r"(a[2]), "r"(a[3]), "r"(b0), "r"(b1));
}
__device__ __forceinline__ void cp_async16(uint32_t dst, const void* src) {
    asm volatile("cp.async.cg.shared.global [%0], [%1], 16;"
                 :: "r"(dst), "l"(src) : "memory");
}

// ---------------------------------------------------------------------------
// K0a: g_W2h[u][d] = fp16(W2[d][u])
// ---------------------------------------------------------------------------
__global__ void w2h_kernel(const float* __restrict__ W2) {
    __shared__ float tile[32][33];
    int d0 = blockIdx.x * 32, u0 = blockIdx.y * 32;
    int tx = threadIdx.x, ty = threadIdx.y;   // 32 x 8
    for (int i = ty; i < 32; i += 8)
        tile[i][tx] = W2[(size_t)(d0 + i) * U + u0 + tx];
    __syncthreads();
    for (int i = ty; i < 32; i += 8)
        g_W2h[(size_t)(u0 + i) * D + d0 + tx] = __float2half(tile[tx][i]);
}

// K0b: zero the score accumulator
__global__ void zero_scores() {
    g_scores[blockIdx.x * 512 + threadIdx.x] = 0.f;
}

// ---------------------------------------------------------------------------
// K1: Q = query @ W1
// ---------------------------------------------------------------------------
__global__ void q_kernel(const float* __restrict__ query,
                         const float* __restrict__ W1) {
    int b = blockIdx.x;
    int tid = threadIdx.x;
    __shared__ float qs[D];
    qs[tid] = query[b * D + tid];
    __syncthreads();
    float acc = 0.f;
#pragma unroll 8
    for (int d = 0; d < D; ++d) acc += qs[d] * W1[d * U + tid];
    g_Q[b * U + tid] = acc;
}

// ---------------------------------------------------------------------------
// K2: scores via mma.sync fp16 (HMMA). CTA tile 128(M=S) x 256(N=U), K=512.
// 3-stage smem pipeline. A rows / B rows padded to 80 B (conflict-free LDSM).
// Epilogue: tanh(Q + C) . V1 reduced into g_scores via atomics.
// ---------------------------------------------------------------------------
#define STAGE_BYTES 30720   // A 128*80 = 10240, B 256*80 = 20480
#define A_OFF 0
#define B_OFF 10240
#define RED_OFF 92160
#define QS_OFF  92672
#define V1_OFF  94720
#define SMEM_TOTAL 96768

__global__ void __launch_bounds__(512, 1) scores_mma(
    const float* __restrict__ values, const float* __restrict__ V1) {
    extern __shared__ char sm[];
    uint32_t smb = smem_u32(sm);
    int tid = threadIdx.x, wid = tid >> 5, lid = tid & 31;
    int b = blockIdx.z, s0 = blockIdx.x * 128, n0 = blockIdx.y * 256;
    int wm = wid >> 3, wn = wid & 7;       // warp grid 2(M) x 8(N)

    const float*  aptr = values + ((size_t)b * S + s0) * D;
    const __half* bptr = g_W2h + (size_t)n0 * D;

    // stage Q, V1; zero reduction buffer
    ((float*)(sm + QS_OFF))[tid] = g_Q[b * U + tid];
    ((float*)(sm + V1_OFF))[tid] = V1[tid];
    if (tid < 128) ((float*)(sm + RED_OFF))[tid] = 0.f;

    float acc[4][4][4];
#pragma unroll
    for (int mt = 0; mt < 4; ++mt)
#pragma unroll
        for (int nt = 0; nt < 4; ++nt)
#pragma unroll
            for (int r = 0; r < 4; ++r) acc[mt][nt][r] = 0.f;

    // ldmatrix lane offsets
    int lr = lid & 7, li = lid >> 3;
    uint32_t a_lane = (uint32_t)(wm * 64 + lr + (li & 1) * 8) * 80
                    + (uint32_t)((li >> 1) * 8) * 2;
    uint32_t b_lane = (uint32_t)(wn * 32 + lr + (li >> 1) * 8) * 80
                    + (uint32_t)((li & 1) * 8) * 2;

    int a_row = tid >> 3, a_cg = tid & 7;   // A loader: 2 float4 per thread
    int b_n   = tid >> 2, b_c  = tid & 3;   // B loader: 2 x 16B per thread

    // ---- prologue: fill stages 0 and 1 ----
#pragma unroll
    for (int ps = 0; ps < 2; ++ps) {
        int k0 = ps * 32;
        char* abase = sm + ps * STAGE_BYTES;
#pragma unroll
        for (int i = 0; i < 2; ++i) {
            int row = a_row + i * 64, cg = a_cg;
            float4 v = *(const float4*)(aptr + (size_t)row * D + k0 + cg * 4);
            *(__half2*)(abase + row * 80 + cg * 8)     = __floats2half2_rn(v.x, v.y);
            *(__half2*)(abase + row * 80 + cg * 8 + 4) = __floats2half2_rn(v.z, v.w);
        }
#pragma unroll
        for (int i = 0; i < 2; ++i) {
            int n = b_n + i * 128, c = b_c;
            cp_async16(smb + ps * STAGE_BYTES + B_OFF + n * 80 + c * 16,
                       bptr + (size_t)n * D + k0 + c * 8);
        }
        asm volatile("cp.async.commit_group;" ::: "memory");
    }
    asm volatile("cp.async.wait_group 1;" ::: "memory");
    __syncthreads();

    // ---- main loop ----
    for (int s = 0; s < 16; ++s) {
        int stg = s % 3;
        // prefetch A for stage s+2 into regs
        float4 pa0, pa1;
        if (s < 14) {
            int k0 = (s + 2) * 32;
            pa0 = *(const float4*)(aptr + (size_t)a_row * D + k0 + a_cg * 4);
            pa1 = *(const float4*)(aptr + (size_t)(a_row + 64) * D + k0 + a_cg * 4);
        }

        // compute stage s
        {
            uint32_t ab = smb + stg * STAGE_BYTES + A_OFF;
            uint32_t bb = smb + stg * STAGE_BYTES + B_OFF;
#pragma unroll
            for (int ks = 0; ks < 2; ++ks) {
                uint32_t koff = ks * 32;
                uint32_t a[4][4], bf[2][4];
#pragma unroll
                for (int mt = 0; mt < 4; ++mt)
                    ldsm_x4(a[mt], ab + a_lane + koff + mt * 16 * 80);
#pragma unroll
                for (int bt = 0; bt < 2; ++bt)
                    ldsm_x4(bf[bt], bb + b_lane + koff + bt * 16 * 80);
#pragma unroll
                for (int mt = 0; mt < 4; ++mt) {
                    mma16816(acc[mt][0], a[mt], bf[0][0], bf[0][1]);
                    mma16816(acc[mt][1], a[mt], bf[0][2], bf[0][3]);
                    mma16816(acc[mt][2], a[mt], bf[1][0], bf[1][1]);
                    mma16816(acc[mt][3], a[mt], bf[1][2], bf[1][3]);
                }
            }
        }

        // store A + issue B cp.async for stage s+2
        if (s < 14) {
            int st2 = (s + 2) % 3;
            int k0 = (s + 2) * 32;
            char* abase = sm + st2 * STAGE_BYTES;
            *(__half2*)(abase + a_row * 80 + a_cg * 8)            = __floats2half2_rn(pa0.x, pa0.y);
            *(__half2*)(abase + a_row * 80 + a_cg * 8 + 4)        = __floats2half2_rn(pa0.z, pa0.w);
            *(__half2*)(abase + (a_row + 64) * 80 + a_cg * 8)     = __floats2half2_rn(pa1.x, pa1.y);
            *(__half2*)(abase + (a_row + 64) * 80 + a_cg * 8 + 4) = __floats2half2_rn(pa1.z, pa1.w);
#pragma unroll
            for (int i = 0; i < 2; ++i) {
                int n = b_n + i * 128, c = b_c;
                cp_async16(smb + st2 * STAGE_BYTES + B_OFF + n * 80 + c * 16,
                           bptr + (size_t)n * D + k0 + c * 8);
            }
        }
        asm volatile("cp.async.commit_group;" ::: "memory");
        asm volatile("cp.async.wait_group 1;" ::: "memory");
        __syncthreads();
    }

    // ---- epilogue: p = sum_u V1[u] * tanh(Q[u] + C[s][u]) ----
    const float* qs  = (const float*)(sm + QS_OFF);
    const float* v1s = (const float*)(sm + V1_OFF);
    float* red = (float*)(sm + RED_OFF);
#pragma unroll
    for (int mt = 0; mt < 4; ++mt) {
        float slo = 0.f, shi = 0.f;
#pragma unroll
        for (int nt = 0; nt < 4; ++nt) {
            int gn = n0 + wn * 32 + nt * 8 + 2 * (lid & 3);
            float q0 = qs[gn], q1 = qs[gn + 1];
            float w0 = v1s[gn], w1 = v1s[gn + 1];
            slo += w0 * tanh_apx(acc[mt][nt][0] + q0) + w1 * tanh_apx(acc[mt][nt][1] + q1);
            shi += w0 * tanh_apx(acc[mt][nt][2] + q0) + w1 * tanh_apx(acc[mt][nt][3] + q1);
        }
        slo += __shfl_xor_sync(0xffffffffu, slo, 1);
        slo += __shfl_xor_sync(0xffffffffu, slo, 2);
        shi += __shfl_xor_sync(0xffffffffu, shi, 1);
        shi += __shfl_xor_sync(0xffffffffu, shi, 2);
        if ((lid & 3) == 0) {
            int row = wm * 64 + mt * 16 + (lid >> 2);
            atomicAdd(red + row, slo);
            atomicAdd(red + row + 8, shi);
        }
    }
    __syncthreads();
    if (tid < 128) atomicAdd(&g_scores[b * S + s0 + tid], red[tid]);
}

// ---------------------------------------------------------------------------
// K3a: per-batch softmax over S -> weights g_w
// ---------------------------------------------------------------------------
__global__ void softmax_kernel() {
    int b = blockIdx.x;
    int tid = threadIdx.x;
    __shared__ float smx[S];
    __shared__ float red[16];
    const float* sc = g_scores + b * S;

    float lmax = -1e30f;
    for (int i = tid; i < S; i += 512) {
        float v = sc[i];
        smx[i] = v;
        lmax = fmaxf(lmax, v);
    }
#pragma unroll
    for (int off = 16; off; off >>= 1)
        lmax = fmaxf(lmax, __shfl_xor_sync(0xffffffffu, lmax, off));
    if ((tid & 31) == 0) red[tid >> 5] = lmax;
    __syncthreads();
    float m = -1e30f;
#pragma unroll
    for (int i = 0; i < 16; ++i) m = fmaxf(m, red[i]);
    __syncthreads();

    float lsum = 0.f;
    for (int i = tid; i < S; i += 512) {
        float e = expf(smx[i] - m);
        smx[i] = e;
        lsum += e;
    }
#pragma unroll
    for (int off = 16; off; off >>= 1)
        lsum += __shfl_xor_sync(0xffffffffu, lsum, off);
    if ((tid & 31) == 0) red[tid >> 5] = lsum;
    __syncthreads();
    float tot = 0.f;
#pragma unroll
    for (int i = 0; i < 16; ++i) tot += red[i];
    float inv = 1.f / tot;
    for (int i = tid; i < S; i += 512) g_w[b * S + i] = smx[i] * inv;
}

// ---------------------------------------------------------------------------
// K3b: partial context
// ---------------------------------------------------------------------------
__global__ void context_partial(const float* __restrict__ values) {
    int split = blockIdx.x;   // 0..7
    int b = blockIdx.y;
    int tid = threadIdx.x;    // d index
    const float* wb = g_w + b * S + split * 256;
    const float* vb = values + ((size_t)b * S + (size_t)split * 256) * D + tid;
    float acc = 0.f;
#pragma unroll 4
    for (int s = 0; s < 256; ++s) acc += wb[s] * vb[(size_t)s * D];
    g_part[(b * 8 + split) * D + tid] = acc;
}

// ---------------------------------------------------------------------------
// K3c: reduce partials -> output (B x D)
// ---------------------------------------------------------------------------
__global__ void context_reduce(float* __restrict__ out) {
    int b = blockIdx.x;
    int tid = threadIdx.x;
    float acc = 0.f;
#pragma unroll
    for (int i = 0; i < 8; ++i) acc += g_part[(b * 8 + i) * D + tid];
    out[b * D + tid] = acc;
}

// ---------------------------------------------------------------------------
extern "C" void kernel_launch(void* const* d_in, const int* in_sizes, int n_in,
                              void* d_out, int out_size) {
    const float* query  = (const float*)d_in[0];   // (B, D)
    const float* values = (const float*)d_in[1];   // (B, S, D)
    const float* W1     = (const float*)d_in[2];   // (D, U)
    const float* W2     = (const float*)d_in[3];   // (D, U)
    const float* V1     = (const float*)d_in[4];   // (U, 1)
    float* out = (float*)d_out;                    // (B, D)

    cudaFuncSetAttribute(scores_mma, cudaFuncAttributeMaxDynamicSharedMemorySize,
                         SMEM_TOTAL);

    w2h_kernel<<<dim3(16, 16), dim3(32, 8)>>>(W2);
    q_kernel<<<B, 512>>>(query, W1);
    zero_scores<<<B * S / 512, 512>>>();
    scores_mma<<<dim3(S / 128, U / 256, B), 512, SMEM_TOTAL>>>(values, V1);
    softmax_kernel<<<B, 512>>>();
    context_partial<<<dim3(8, B), 512>>>(values);
    context_reduce<<<B, 512>>>(out);
}

// round 10
// speedup vs baseline: 6.1606x; 1.0145x over previous
#include <cuda_runtime.h>
#include <cuda_fp16.h>
#include <cstdint>

#define B 64
#define S 2048
#define D 512
#define U 512

// Scratch (allocation-free rule: __device__ globals)
__device__ float  g_Q[B * U];         // query @ W1
__device__ __half g_W2h[U * D];       // W2 transposed to (U, D), fp16
__device__ float  g_scores[B * S];    // pre-softmax scores (atomically accumulated)
__device__ float  g_w[B * S];         // softmax weights
__device__ float  g_part[B * 32 * D]; // partial contexts (8 splits x 4 sgroups)

// ---------------------------------------------------------------------------
// Helpers
// ---------------------------------------------------------------------------
__device__ __forceinline__ uint32_t smem_u32(const void* p) {
    uint32_t a;
    asm("{ .reg .u64 t; cvta.to.shared.u64 t, %1; cvt.u32.u64 %0, t; }"
        : "=r"(a) : "l"(p));
    return a;
}
__device__ __forceinline__ float tanh_apx(float x) {
    float y; asm("tanh.approx.f32 %0, %1;" : "=f"(y) : "f"(x)); return y;
}
__device__ __forceinline__ void ldsm_x4(uint32_t* r, uint32_t addr) {
    asm volatile("ldmatrix.sync.aligned.m8n8.x4.shared.b16 {%0,%1,%2,%3}, [%4];"
                 : "=r"(r[0]), "=r"(r[1]), "=r"(r[2]), "=r"(r[3]) : "r"(addr));
}
__device__ __forceinline__ void mma16816(float* c, const uint32_t* a,
                                         uint32_t b0, uint32_t b1) {
    asm volatile(
        "mma.sync.aligned.m16n8k16.row.col.f32.f16.f16.f32 "
        "{%0,%1,%2,%3}, {%4,%5,%6,%7}, {%8,%9}, {%0,%1,%2,%3};"
        : "+f"(c[0]), "+f"(c[1]), "+f"(c[2]), "+f"(c[3])
        : "r"(a[0]), "r"(a[1]), "r"(a[2]), "r"(a[3]), "r"(b0), "r"(b1));
}
__device__ __forceinline__ void cp_async16(uint32_t dst, const void* src) {
    asm volatile("cp.async.cg.shared.global [%0], [%1], 16;"
                 :: "r"(dst), "l"(src) : "memory");
}

// ---------------------------------------------------------------------------
// K0a: g_W2h[u][d] = fp16(W2[d][u])
// ---------------------------------------------------------------------------
__global__ void w2h_kernel(const float* __restrict__ W2) {
    __shared__ float tile[32][33];
    int d0 = blockIdx.x * 32, u0 = blockIdx.y * 32;
    int tx = threadIdx.x, ty = threadIdx.y;   // 32 x 8
    for (int i = ty; i < 32; i += 8)
        tile[i][tx] = W2[(size_t)(d0 + i) * U + u0 + tx];
    __syncthreads();
    for (int i = ty; i < 32; i += 8)
        g_W2h[(size_t)(u0 + i) * D + d0 + tx] = __float2half(tile[tx][i]);
}

// K0b: zero the score accumulator
__global__ void zero_scores() {
    g_scores[blockIdx.x * 512 + threadIdx.x] = 0.f;
}

// ---------------------------------------------------------------------------
// K1: Q = query @ W1
// ---------------------------------------------------------------------------
__global__ void q_kernel(const float* __restrict__ query,
                         const float* __restrict__ W1) {
    int b = blockIdx.x;
    int tid = threadIdx.x;
    __shared__ float qs[D];
    qs[tid] = query[b * D + tid];
    __syncthreads();
    float acc = 0.f;
#pragma unroll 8
    for (int d = 0; d < D; ++d) acc += qs[d] * W1[d * U + tid];
    g_Q[b * U + tid] = acc;
}

// ---------------------------------------------------------------------------
// K2: scores via mma.sync fp16. CTA tile 128(M) x 128(N), 256 threads,
// 3-stage pipeline, 2 CTAs/SM. Warp grid 2(M) x 4(N), warp tile 64x32.
// Epilogue: tanh(Q + C) . V1 reduced into g_scores via atomics.
// ---------------------------------------------------------------------------
#define STAGE_BYTES 20480   // A 128*80 = 10240, B 128*80 = 10240
#define A_OFF 0
#define B_OFF 10240
#define RED_OFF 61440
#define QS_OFF  61952
#define V1_OFF  64000
#define SMEM_TOTAL 66048

__global__ void __launch_bounds__(256, 2) scores_mma(
    const float* __restrict__ values, const float* __restrict__ V1) {
    extern __shared__ char sm[];
    uint32_t smb = smem_u32(sm);
    int tid = threadIdx.x, wid = tid >> 5, lid = tid & 31;
    int b = blockIdx.z, s0 = blockIdx.x * 128, n0 = blockIdx.y * 128;
    int wm = wid >> 2, wn = wid & 3;       // warp grid 2(M) x 4(N)

    const float*  aptr = values + ((size_t)b * S + s0) * D;
    const __half* bptr = g_W2h + (size_t)n0 * D;

    // stage Q, V1; zero reduction buffer
#pragma unroll
    for (int i = 0; i < 2; ++i) {
        ((float*)(sm + QS_OFF))[tid + 256 * i] = g_Q[b * U + tid + 256 * i];
        ((float*)(sm + V1_OFF))[tid + 256 * i] = V1[tid + 256 * i];
    }
    if (tid < 128) ((float*)(sm + RED_OFF))[tid] = 0.f;

    float acc[4][4][4];
#pragma unroll
    for (int mt = 0; mt < 4; ++mt)
#pragma unroll
        for (int nt = 0; nt < 4; ++nt)
#pragma unroll
            for (int r = 0; r < 4; ++r) acc[mt][nt][r] = 0.f;

    // ldmatrix lane offsets
    int lr = lid & 7, li = lid >> 3;
    uint32_t a_lane = (uint32_t)(wm * 64 + lr + (li & 1) * 8) * 80
                    + (uint32_t)((li >> 1) * 8) * 2;
    uint32_t b_lane = (uint32_t)(wn * 32 + lr + (li >> 1) * 8) * 80
                    + (uint32_t)((li & 1) * 8) * 2;

    int a_row = tid >> 3, a_cg = tid & 7;   // A loader: 4 float4 per thread (rows +32*i)
    int b_n   = tid >> 2, b_c  = tid & 3;   // B loader: 2 x 16B per thread (n +64*i)

    // ---- prologue: fill stages 0 and 1 ----
#pragma unroll
    for (int ps = 0; ps < 2; ++ps) {
        int k0 = ps * 32;
        char* abase = sm + ps * STAGE_BYTES;
#pragma unroll
        for (int i = 0; i < 4; ++i) {
            int row = a_row + i * 32, cg = a_cg;
            float4 v = *(const float4*)(aptr + (size_t)row * D + k0 + cg * 4);
            *(__half2*)(abase + row * 80 + cg * 8)     = __floats2half2_rn(v.x, v.y);
            *(__half2*)(abase + row * 80 + cg * 8 + 4) = __floats2half2_rn(v.z, v.w);
        }
#pragma unroll
        for (int i = 0; i < 2; ++i) {
            int n = b_n + i * 64, c = b_c;
            cp_async16(smb + ps * STAGE_BYTES + B_OFF + n * 80 + c * 16,
                       bptr + (size_t)n * D + k0 + c * 8);
        }
        asm volatile("cp.async.commit_group;" ::: "memory");
    }
    asm volatile("cp.async.wait_group 1;" ::: "memory");
    __syncthreads();

    // ---- main loop ----
    for (int s = 0; s < 16; ++s) {
        int stg = s % 3;
        // prefetch A for stage s+2 into regs
        float4 pa[4];
        if (s < 14) {
            int k0 = (s + 2) * 32;
#pragma unroll
            for (int i = 0; i < 4; ++i)
                pa[i] = *(const float4*)(aptr + (size_t)(a_row + i * 32) * D + k0 + a_cg * 4);
        }

        // compute stage s
        {
            uint32_t ab = smb + stg * STAGE_BYTES + A_OFF;
            uint32_t bb = smb + stg * STAGE_BYTES + B_OFF;
#pragma unroll
            for (int ks = 0; ks < 2; ++ks) {
                uint32_t koff = ks * 32;
                uint32_t a[4][4], bf[2][4];
#pragma unroll
                for (int mt = 0; mt < 4; ++mt)
                    ldsm_x4(a[mt], ab + a_lane + koff + mt * 16 * 80);
#pragma unroll
                for (int bt = 0; bt < 2; ++bt)
                    ldsm_x4(bf[bt], bb + b_lane + koff + bt * 16 * 80);
#pragma unroll
                for (int mt = 0; mt < 4; ++mt) {
                    mma16816(acc[mt][0], a[mt], bf[0][0], bf[0][1]);
                    mma16816(acc[mt][1], a[mt], bf[0][2], bf[0][3]);
                    mma16816(acc[mt][2], a[mt], bf[1][0], bf[1][1]);
                    mma16816(acc[mt][3], a[mt], bf[1][2], bf[1][3]);
                }
            }
        }

        // store A + issue B cp.async for stage s+2
        if (s < 14) {
            int st2 = (s + 2) % 3;
            int k0 = (s + 2) * 32;
            char* abase = sm + st2 * STAGE_BYTES;
#pragma unroll
            for (int i = 0; i < 4; ++i) {
                int row = a_row + i * 32;
                *(__half2*)(abase + row * 80 + a_cg * 8)     = __floats2half2_rn(pa[i].x, pa[i].y);
                *(__half2*)(abase + row * 80 + a_cg * 8 + 4) = __floats2half2_rn(pa[i].z, pa[i].w);
            }
#pragma unroll
            for (int i = 0; i < 2; ++i) {
                int n = b_n + i * 64, c = b_c;
                cp_async16(smb + st2 * STAGE_BYTES + B_OFF + n * 80 + c * 16,
                           bptr + (size_t)n * D + k0 + c * 8);
            }
        }
        asm volatile("cp.async.commit_group;" ::: "memory");
        asm volatile("cp.async.wait_group 1;" ::: "memory");
        __syncthreads();
    }

    // ---- epilogue: p = sum_u V1[u] * tanh(Q[u] + C[s][u]) ----
    const float* qs  = (const float*)(sm + QS_OFF);
    const float* v1s = (const float*)(sm + V1_OFF);
    float* red = (float*)(sm + RED_OFF);
#pragma unroll
    for (int mt = 0; mt < 4; ++mt) {
        float slo = 0.f, shi = 0.f;
#pragma unroll
        for (int nt = 0; nt < 4; ++nt) {
            int gn = wn * 32 + nt * 8 + 2 * (lid & 3);   // local col in [0,128)
            float q0 = qs[n0 + gn], q1 = qs[n0 + gn + 1];
            float w0 = v1s[n0 + gn], w1 = v1s[n0 + gn + 1];
            slo += w0 * tanh_apx(acc[mt][nt][0] + q0) + w1 * tanh_apx(acc[mt][nt][1] + q1);
            shi += w0 * tanh_apx(acc[mt][nt][2] + q0) + w1 * tanh_apx(acc[mt][nt][3] + q1);
        }
        slo += __shfl_xor_sync(0xffffffffu, slo, 1);
        slo += __shfl_xor_sync(0xffffffffu, slo, 2);
        shi += __shfl_xor_sync(0xffffffffu, shi, 1);
        shi += __shfl_xor_sync(0xffffffffu, shi, 2);
        if ((lid & 3) == 0) {
            int row = wm * 64 + mt * 16 + (lid >> 2);
            atomicAdd(red + row, slo);
            atomicAdd(red + row + 8, shi);
        }
    }
    __syncthreads();
    if (tid < 128) atomicAdd(&g_scores[b * S + s0 + tid], red[tid]);
}

// ---------------------------------------------------------------------------
// K3a: per-batch softmax over S -> weights g_w
// ---------------------------------------------------------------------------
__global__ void softmax_kernel() {
    int b = blockIdx.x;
    int tid = threadIdx.x;
    __shared__ float smx[S];
    __shared__ float red[16];
    const float* sc = g_scores + b * S;

    float lmax = -1e30f;
    for (int i = tid; i < S; i += 512) {
        float v = sc[i];
        smx[i] = v;
        lmax = fmaxf(lmax, v);
    }
#pragma unroll
    for (int off = 16; off; off >>= 1)
        lmax = fmaxf(lmax, __shfl_xor_sync(0xffffffffu, lmax, off));
    if ((tid & 31) == 0) red[tid >> 5] = lmax;
    __syncthreads();
    float m = -1e30f;
#pragma unroll
    for (int i = 0; i < 16; ++i) m = fmaxf(m, red[i]);
    __syncthreads();

    float lsum = 0.f;
    for (int i = tid; i < S; i += 512) {
        float e = expf(smx[i] - m);
        smx[i] = e;
        lsum += e;
    }
#pragma unroll
    for (int off = 16; off; off >>= 1)
        lsum += __shfl_xor_sync(0xffffffffu, lsum, off);
    if ((tid & 31) == 0) red[tid >> 5] = lsum;
    __syncthreads();
    float tot = 0.f;
#pragma unroll
    for (int i = 0; i < 16; ++i) tot += red[i];
    float inv = 1.f / tot;
    for (int i = tid; i < S; i += 512) g_w[b * S + i] = smx[i] * inv;
}

// ---------------------------------------------------------------------------
// K3b: partial context, float4 version.
// grid (8, B), 512 threads: d4 = tid&127 (float4 lane), sgrp = tid>>7 (0..3).
// Each thread: 64 rows, 4 independent FFMA chains (float4 acc).
// ---------------------------------------------------------------------------
__global__ void context_partial(const float* __restrict__ values) {
    int split = blockIdx.x;   // 0..7
    int b = blockIdx.y;
    int tid = threadIdx.x;
    int d4 = tid & 127, sgrp = tid >> 7;
    int srow0 = split * 256 + sgrp * 64;
    const float* wb = g_w + b * S + srow0;
    const float4* vb = (const float4*)(values + ((size_t)b * S + srow0) * D) + d4;
    float4 acc = make_float4(0.f, 0.f, 0.f, 0.f);
#pragma unroll 4
    for (int s = 0; s < 64; ++s) {
        float w = wb[s];
        float4 v = vb[(size_t)s * (D / 4)];
        acc.x += w * v.x; acc.y += w * v.y;
        acc.z += w * v.z; acc.w += w * v.w;
    }
    ((float4*)(g_part + (size_t)((b * 8 + split) * 4 + sgrp) * D))[d4] = acc;
}

// ---------------------------------------------------------------------------
// K3c: reduce 32 partials -> output (B x D)
// ---------------------------------------------------------------------------
__global__ void context_reduce(float* __restrict__ out) {
    int b = blockIdx.x;
    int tid = threadIdx.x;
    float acc = 0.f;
#pragma unroll
    for (int i = 0; i < 32; ++i) acc += g_part[(size_t)(b * 32 + i) * D + tid];
    out[b * D + tid] = acc;
}

// ---------------------------------------------------------------------------
extern "C" void kernel_launch(void* const* d_in, const int* in_sizes, int n_in,
                              void* d_out, int out_size) {
    const float* query  = (const float*)d_in[0];   // (B, D)
    const float* values = (const float*)d_in[1];   // (B, S, D)
    const float* W1     = (const float*)d_in[2];   // (D, U)
    const float* W2     = (const float*)d_in[3];   // (D, U)
    const float* V1     = (const float*)d_in[4];   // (U, 1)
    float* out = (float*)d_out;                    // (B, D)

    cudaFuncSetAttribute(scores_mma, cudaFuncAttributeMaxDynamicSharedMemorySize,
                         SMEM_TOTAL);

    w2h_kernel<<<dim3(16, 16), dim3(32, 8)>>>(W2);
    q_kernel<<<B, 512>>>(query, W1);
    zero_scores<<<B * S / 512, 512>>>();
    scores_mma<<<dim3(S / 128, U / 128, B), 256, SMEM_TOTAL>>>(values, V1);
    softmax_kernel<<<B, 512>>>();
    context_partial<<<dim3(8, B), 512>>>(values);
    context_reduce<<<B, 512>>>(out);
}